// round 5
// baseline (speedup 1.0000x reference)
#include <cuda_runtime.h>
#include <cuda_bf16.h>
#include <cstdint>

#define N_NODES 100000
#define D 32

// 12.8 MB scratch for the aggregation result (allocation-free per harness rules)
__device__ float g_agg[N_NODES * D];

// ---------------------------------------------------------------------------
// Scatter: 8 lanes per edge, 4 edges per warp. Each lane gathers one float4
// of the 128B source row (coalesced within the 8-lane group) and issues a
// single vectorized red.global.add.v4.f32 into agg[dst].
// edge_index arrives as int32.
// ---------------------------------------------------------------------------
__global__ void scatter_kernel(const float4* __restrict__ x4,
                               const int* __restrict__ edge_index,
                               float* __restrict__ agg,
                               int n_edges) {
    int lane = threadIdx.x & 31;
    int sub  = lane >> 3;   // which of the 4 edges this warp handles
    int q    = lane & 7;    // which 16B quarter of the 128B row

    int warp0   = (blockIdx.x * blockDim.x + threadIdx.x) >> 5;
    int wstride = (gridDim.x * blockDim.x) >> 5;

    for (int e0 = warp0 * 4; e0 < n_edges; e0 += wstride * 4) {
        int e = e0 + sub;
        if (e < n_edges) {
            int src = __ldg(edge_index + e);            // row 0: src
            int dst = __ldg(edge_index + n_edges + e);  // row 1: dst

            float4 v = __ldg(&x4[(size_t)src * 8 + q]);
            float* p = agg + (size_t)dst * D + q * 4;
            asm volatile(
                "red.global.add.v4.f32 [%0], {%1, %2, %3, %4};"
                :: "l"(p), "f"(v.x), "f"(v.y), "f"(v.z), "f"(v.w)
                : "memory");
        }
    }
}

// ---------------------------------------------------------------------------
// GEMM: out = agg @ W^T, W is [32, 32].
// One warp per node. Lane j keeps W row j in registers; lane k loads
// agg[node][k] (coalesced); 32x (shfl-broadcast + FFMA); coalesced store.
// No shared memory at all.
// ---------------------------------------------------------------------------
__global__ void gemm_kernel(const float* __restrict__ agg,
                            const float* __restrict__ W,
                            float* __restrict__ out,
                            int n_nodes) {
    int lane = threadIdx.x & 31;

    // Lane j holds W[j][0..31] in registers (loaded once per thread).
    float w[D];
#pragma unroll
    for (int k = 0; k < D; ++k) w[k] = __ldg(&W[lane * D + k]);

    int warp0   = (blockIdx.x * blockDim.x + threadIdx.x) >> 5;
    int wstride = (gridDim.x * blockDim.x) >> 5;

    for (int node = warp0; node < n_nodes; node += wstride) {
        float a = agg[(size_t)node * D + lane];   // coalesced 128B row
        float acc = 0.0f;
#pragma unroll
        for (int k = 0; k < D; ++k)
            acc = fmaf(__shfl_sync(0xffffffffu, a, k), w[k], acc);
        out[(size_t)node * D + lane] = acc;       // coalesced
    }
}

// ---------------------------------------------------------------------------
extern "C" void kernel_launch(void* const* d_in, const int* in_sizes, int n_in,
                              void* d_out, int out_size) {
    const float* x = (const float*)d_in[0];
    const int* edge_index = (const int*)d_in[1];
    const float* W = (const float*)d_in[2];
    float* out = (float*)d_out;

    int n_edges = in_sizes[1] / 2;
    int n_nodes = in_sizes[0] / D;

    float* agg;
    cudaGetSymbolAddress((void**)&agg, g_agg);

    // 1) zero the aggregation buffer
    cudaMemsetAsync(agg, 0, (size_t)N_NODES * D * sizeof(float));

    // 2) scatter-add: 4 edges per warp, vector RED, persistent grid
    {
        int threads = 256;   // 8 warps
        int blocks  = 4736;  // 32 blocks/SM worth; grid-stride covers 1.6M edges
        scatter_kernel<<<blocks, threads>>>((const float4*)x, edge_index, agg,
                                            n_edges);
    }

    // 3) GEMM: warp per node, shuffle broadcast, persistent grid
    {
        int threads = 256;
        int blocks  = 2048;
        gemm_kernel<<<blocks, threads>>>(agg, W, out, n_nodes);
    }
}

// round 6
// speedup vs baseline: 1.1671x; 1.1671x over previous
#include <cuda_runtime.h>
#include <cuda_bf16.h>
#include <cstdint>

#define N_NODES 100000
#define D 32

// 12.8 MB scratch for the aggregation result (allocation-free per harness rules)
__device__ float g_agg[N_NODES * D];

// ---------------------------------------------------------------------------
// Scatter: 8 lanes per edge, 4 edges per warp. Each lane gathers one float4
// of the 128B source row and issues a vectorized red.global.add.v4.f32.
// ---------------------------------------------------------------------------
__global__ void scatter_kernel(const float4* __restrict__ x4,
                               const int* __restrict__ edge_index,
                               float* __restrict__ agg,
                               int n_edges) {
    int lane = threadIdx.x & 31;
    int sub  = lane >> 3;   // which of the 4 edges this warp handles
    int q    = lane & 7;    // which 16B quarter of the 128B row

    int warp0   = (blockIdx.x * blockDim.x + threadIdx.x) >> 5;
    int wstride = (gridDim.x * blockDim.x) >> 5;

    for (int e0 = warp0 * 4; e0 < n_edges; e0 += wstride * 4) {
        int e = e0 + sub;
        if (e < n_edges) {
            int src = __ldg(edge_index + e);            // row 0: src
            int dst = __ldg(edge_index + n_edges + e);  // row 1: dst

            float4 v = __ldg(&x4[(size_t)src * 8 + q]);
            float* p = agg + (size_t)dst * D + q * 4;
            asm volatile(
                "red.global.add.v4.f32 [%0], {%1, %2, %3, %4};"
                :: "l"(p), "f"(v.x), "f"(v.y), "f"(v.z), "f"(v.w)
                : "memory");
        }
    }
}

// ---------------------------------------------------------------------------
// GEMM: out = agg @ W^T, W is [32, 32].
// Block = 256 threads = 8 warps; tile = 64 nodes (8 nodes per warp).
// Lane j holds W[j][0..31] in registers. agg tile staged in smem coalesced;
// each node row is then read as 8 broadcast LDS.128 (same addr across lanes).
// 8 independent accumulator chains per thread hide FFMA latency.
// ---------------------------------------------------------------------------
#define TILE_NODES 64

__global__ void gemm_kernel(const float4* __restrict__ agg4,
                            const float* __restrict__ W,
                            float* __restrict__ out,
                            int n_nodes) {
    __shared__ float4 As[TILE_NODES * 8];   // 64 rows x 32 floats = 8KB

    int tid  = threadIdx.x;
    int lane = tid & 31;   // output feature j
    int wid  = tid >> 5;   // warp: handles nodes [wid*8, wid*8+8) of tile

    // W row j in registers
    float w[D];
#pragma unroll
    for (int k = 0; k < D; ++k) w[k] = __ldg(&W[lane * D + k]);

    int tile_base = blockIdx.x * TILE_NODES;

    // Stage agg tile coalesced: 512 float4, 2 per thread
    {
        int nvec = TILE_NODES * 8;   // 512
        for (int i = tid; i < nvec; i += blockDim.x) {
            int node = tile_base + (i >> 3);
            As[i] = (node < n_nodes) ? agg4[(size_t)node * 8 + (i & 7)]
                                     : make_float4(0.f, 0.f, 0.f, 0.f);
        }
    }
    __syncthreads();

    float acc[8];
#pragma unroll
    for (int r = 0; r < 8; ++r) acc[r] = 0.0f;

#pragma unroll
    for (int k4 = 0; k4 < 8; ++k4) {
#pragma unroll
        for (int r = 0; r < 8; ++r) {
            // broadcast read: same address for every lane in the warp
            float4 a = As[(wid * 8 + r) * 8 + k4];
            acc[r] = fmaf(a.x, w[k4 * 4 + 0], acc[r]);
            acc[r] = fmaf(a.y, w[k4 * 4 + 1], acc[r]);
            acc[r] = fmaf(a.z, w[k4 * 4 + 2], acc[r]);
            acc[r] = fmaf(a.w, w[k4 * 4 + 3], acc[r]);
        }
    }

#pragma unroll
    for (int r = 0; r < 8; ++r) {
        int node = tile_base + wid * 8 + r;
        if (node < n_nodes)
            out[(size_t)node * D + lane] = acc[r];   // coalesced 128B store
    }
}

// ---------------------------------------------------------------------------
extern "C" void kernel_launch(void* const* d_in, const int* in_sizes, int n_in,
                              void* d_out, int out_size) {
    const float* x = (const float*)d_in[0];
    const int* edge_index = (const int*)d_in[1];
    const float* W = (const float*)d_in[2];
    float* out = (float*)d_out;

    int n_edges = in_sizes[1] / 2;
    int n_nodes = in_sizes[0] / D;

    float* agg;
    cudaGetSymbolAddress((void**)&agg, g_agg);

    // 1) zero the aggregation buffer
    cudaMemsetAsync(agg, 0, (size_t)N_NODES * D * sizeof(float));

    // 2) scatter-add: 4 edges per warp, vector RED, persistent grid
    {
        int threads = 256;   // 8 warps
        int blocks  = 4736;
        scatter_kernel<<<blocks, threads>>>((const float4*)x, edge_index, agg,
                                            n_edges);
    }

    // 3) GEMM: 64 nodes per block
    {
        int blocks = (n_nodes + TILE_NODES - 1) / TILE_NODES;  // 1563
        gemm_kernel<<<blocks, 256>>>((const float4*)agg, W, out, n_nodes);
    }
}

// round 7
// speedup vs baseline: 1.3390x; 1.1473x over previous
#include <cuda_runtime.h>
#include <cuda_bf16.h>
#include <cstdint>

#define N_NODES 100000
#define D 32

// 12.8 MB scratch for the aggregation result (allocation-free per harness rules)
__device__ float g_agg[N_NODES * D];

// ---------------------------------------------------------------------------
// Scatter: 8 lanes per edge, 4 edges per warp. Each lane gathers one float4
// of the 128B source row and issues a vectorized red.global.add.v4.f32.
// At the L2 throughput floor (~410MB gather+RED traffic).
// ---------------------------------------------------------------------------
__global__ void scatter_kernel(const float4* __restrict__ x4,
                               const int* __restrict__ edge_index,
                               float* __restrict__ agg,
                               int n_edges) {
    int lane = threadIdx.x & 31;
    int sub  = lane >> 3;   // which of the 4 edges this warp handles
    int q    = lane & 7;    // which 16B quarter of the 128B row

    int warp0   = (blockIdx.x * blockDim.x + threadIdx.x) >> 5;
    int wstride = (gridDim.x * blockDim.x) >> 5;

    for (int e0 = warp0 * 4; e0 < n_edges; e0 += wstride * 4) {
        int e = e0 + sub;
        if (e < n_edges) {
            int src = __ldg(edge_index + e);            // row 0: src
            int dst = __ldg(edge_index + n_edges + e);  // row 1: dst

            float4 v = __ldg(&x4[(size_t)src * 8 + q]);
            float* p = agg + (size_t)dst * D + q * 4;
            asm volatile(
                "red.global.add.v4.f32 [%0], {%1, %2, %3, %4};"
                :: "l"(p), "f"(v.x), "f"(v.y), "f"(v.z), "f"(v.w)
                : "memory");
        }
    }
}

// ---------------------------------------------------------------------------
// GEMM: out = agg @ W^T, W is [32, 32].
// Block = 256 threads = 8 warps; tile = 64 nodes (8 nodes per warp).
// W staged COALESCED into padded smem once per block, then lane j copies
// row j into registers via conflict-free LDS. agg tile staged coalesced;
// compute reads node rows as broadcast LDS.128 (N=1). 8 independent
// accumulator chains per thread hide FFMA latency.
// ---------------------------------------------------------------------------
#define TILE_NODES 64

__global__ __launch_bounds__(256)
void gemm_kernel(const float4* __restrict__ agg4,
                 const float* __restrict__ W,
                 float* __restrict__ out,
                 int n_nodes) {
    __shared__ float4 As[TILE_NODES * 8];   // 64 rows x 32 floats = 8KB
    __shared__ float  Ws[D * 33];           // padded, conflict-free

    int tid  = threadIdx.x;
    int lane = tid & 31;   // output feature j
    int wid  = tid >> 5;   // warp: handles nodes [wid*8, wid*8+8) of tile

    int tile_base = blockIdx.x * TILE_NODES;

    // Stage W coalesced: 1024 floats, 4 per thread
#pragma unroll
    for (int i = tid; i < D * D; i += 256)
        Ws[(i >> 5) * 33 + (i & 31)] = W[i];

    // Stage agg tile coalesced: 512 float4, 2 per thread
    {
        int nvec = TILE_NODES * 8;   // 512
        for (int i = tid; i < nvec; i += blockDim.x) {
            int node = tile_base + (i >> 3);
            As[i] = (node < n_nodes) ? agg4[(size_t)node * 8 + (i & 7)]
                                     : make_float4(0.f, 0.f, 0.f, 0.f);
        }
    }
    __syncthreads();

    // Lane j copies W row j to registers: Ws[j*33+k] -> bank (j+k)%32,
    // distinct across lanes for each k -> conflict-free.
    float w[D];
#pragma unroll
    for (int k = 0; k < D; ++k) w[k] = Ws[lane * 33 + k];

    float acc[8];
#pragma unroll
    for (int r = 0; r < 8; ++r) acc[r] = 0.0f;

#pragma unroll
    for (int k4 = 0; k4 < 8; ++k4) {
#pragma unroll
        for (int r = 0; r < 8; ++r) {
            // broadcast read: same address for every lane in the warp
            float4 a = As[(wid * 8 + r) * 8 + k4];
            acc[r] = fmaf(a.x, w[k4 * 4 + 0], acc[r]);
            acc[r] = fmaf(a.y, w[k4 * 4 + 1], acc[r]);
            acc[r] = fmaf(a.z, w[k4 * 4 + 2], acc[r]);
            acc[r] = fmaf(a.w, w[k4 * 4 + 3], acc[r]);
        }
    }

#pragma unroll
    for (int r = 0; r < 8; ++r) {
        int node = tile_base + wid * 8 + r;
        if (node < n_nodes)
            out[(size_t)node * D + lane] = acc[r];   // coalesced 128B store
    }
}

// ---------------------------------------------------------------------------
extern "C" void kernel_launch(void* const* d_in, const int* in_sizes, int n_in,
                              void* d_out, int out_size) {
    const float* x = (const float*)d_in[0];
    const int* edge_index = (const int*)d_in[1];
    const float* W = (const float*)d_in[2];
    float* out = (float*)d_out;

    int n_edges = in_sizes[1] / 2;
    int n_nodes = in_sizes[0] / D;

    float* agg;
    cudaGetSymbolAddress((void**)&agg, g_agg);

    // 1) zero the aggregation buffer
    cudaMemsetAsync(agg, 0, (size_t)N_NODES * D * sizeof(float));

    // 2) scatter-add: 4 edges per warp, vector RED, persistent grid
    {
        int threads = 256;   // 8 warps
        int blocks  = 4736;
        scatter_kernel<<<blocks, threads>>>((const float4*)x, edge_index, agg,
                                            n_edges);
    }

    // 3) GEMM: 64 nodes per block
    {
        int blocks = (n_nodes + TILE_NODES - 1) / TILE_NODES;  // 1563
        gemm_kernel<<<blocks, 256>>>((const float4*)agg, W, out, n_nodes);
    }
}

// round 8
// speedup vs baseline: 2.1889x; 1.6347x over previous
#include <cuda_runtime.h>
#include <cuda_bf16.h>
#include <cstdint>

#define N_NODES 100000
#define D 32

// 12.8 MB scratch for the aggregation result (allocation-free per harness rules)
__device__ float g_agg[N_NODES * D];

// ---------------------------------------------------------------------------
// Scatter: 8 lanes per edge, 4 edges per warp. Each lane gathers one float4
// of the 128B source row and issues a vectorized red.global.add.v4.f32.
// At the L2/LTS throughput floor (~410MB gather+RED traffic).
// ---------------------------------------------------------------------------
__global__ void scatter_kernel(const float4* __restrict__ x4,
                               const int* __restrict__ edge_index,
                               float* __restrict__ agg,
                               int n_edges) {
    int lane = threadIdx.x & 31;
    int sub  = lane >> 3;   // which of the 4 edges this warp handles
    int q    = lane & 7;    // which 16B quarter of the 128B row

    int warp0   = (blockIdx.x * blockDim.x + threadIdx.x) >> 5;
    int wstride = (gridDim.x * blockDim.x) >> 5;

    for (int e0 = warp0 * 4; e0 < n_edges; e0 += wstride * 4) {
        int e = e0 + sub;
        if (e < n_edges) {
            int src = __ldg(edge_index + e);            // row 0: src
            int dst = __ldg(edge_index + n_edges + e);  // row 1: dst

            float4 v = __ldg(&x4[(size_t)src * 8 + q]);
            float* p = agg + (size_t)dst * D + q * 4;
            asm volatile(
                "red.global.add.v4.f32 [%0], {%1, %2, %3, %4};"
                :: "l"(p), "f"(v.x), "f"(v.y), "f"(v.z), "f"(v.w)
                : "memory");
        }
    }
}

// ---------------------------------------------------------------------------
// GEMM: out = agg @ W^T, W is [32, 32].
// Persistent blocks, 256 threads = 8 warps; tile = 64 nodes (8 per warp).
// Double-buffered smem tile + register prefetch of the NEXT tile issued
// before compute, so L2 load latency overlaps the 256 FFMAs.
// W staged coalesced into padded smem ONCE per block, then per-lane row
// copy to registers (conflict-free). Compute reads node rows as broadcast
// LDS.128; 8 independent accumulator chains hide FFMA latency.
// ---------------------------------------------------------------------------
#define TILE_NODES 64
#define TILE_VEC   (TILE_NODES * 8)   // 512 float4 per tile

__global__ __launch_bounds__(256)
void gemm_kernel(const float4* __restrict__ agg4,
                 const float* __restrict__ W,
                 float* __restrict__ out,
                 int n_nodes) {
    __shared__ float4 As[2][TILE_VEC];  // 2 x 8KB
    __shared__ float  Ws[D * 33];       // padded, conflict-free

    int tid  = threadIdx.x;
    int lane = tid & 31;   // output feature j
    int wid  = tid >> 5;   // warp: handles nodes [wid*8, wid*8+8) of tile

    // Stage W coalesced (once per block)
#pragma unroll
    for (int i = tid; i < D * D; i += 256)
        Ws[(i >> 5) * 33 + (i & 31)] = W[i];
    __syncthreads();

    // Lane j copies W row j to registers (conflict-free: bank (j+k)%32)
    float w[D];
#pragma unroll
    for (int k = 0; k < D; ++k) w[k] = Ws[lane * 33 + k];

    int ntiles = (n_nodes + TILE_NODES - 1) / TILE_NODES;

    // Prefetch first tile into registers
    float4 p0 = make_float4(0.f, 0.f, 0.f, 0.f), p1 = p0;
    int tile = blockIdx.x;
    if (tile < ntiles) {
        int base = tile * TILE_VEC;
        int i0 = base + tid, i1 = base + tid + 256;
        if ((i0 >> 3) < n_nodes) p0 = __ldg(&agg4[i0]);
        if ((i1 >> 3) < n_nodes) p1 = __ldg(&agg4[i1]);
    }

    int buf = 0;
    for (; tile < ntiles; tile += gridDim.x) {
        // Commit prefetched tile to smem
        As[buf][tid]       = p0;
        As[buf][tid + 256] = p1;
        __syncthreads();

        // Issue NEXT tile's loads before compute (latency overlap)
        int nt = tile + gridDim.x;
        if (nt < ntiles) {
            int base = nt * TILE_VEC;
            int i0 = base + tid, i1 = base + tid + 256;
            p0 = ((i0 >> 3) < n_nodes) ? __ldg(&agg4[i0])
                                       : make_float4(0.f, 0.f, 0.f, 0.f);
            p1 = ((i1 >> 3) < n_nodes) ? __ldg(&agg4[i1])
                                       : make_float4(0.f, 0.f, 0.f, 0.f);
        }

        // Compute 8 nodes per warp
        float acc[8];
#pragma unroll
        for (int r = 0; r < 8; ++r) acc[r] = 0.0f;

        const float4* Ab = &As[buf][wid * 64];
#pragma unroll
        for (int k4 = 0; k4 < 8; ++k4) {
#pragma unroll
            for (int r = 0; r < 8; ++r) {
                float4 a = Ab[r * 8 + k4];   // broadcast across lanes
                acc[r] = fmaf(a.x, w[k4 * 4 + 0], acc[r]);
                acc[r] = fmaf(a.y, w[k4 * 4 + 1], acc[r]);
                acc[r] = fmaf(a.z, w[k4 * 4 + 2], acc[r]);
                acc[r] = fmaf(a.w, w[k4 * 4 + 3], acc[r]);
            }
        }

        int node0 = tile * TILE_NODES + wid * 8;
#pragma unroll
        for (int r = 0; r < 8; ++r) {
            int node = node0 + r;
            if (node < n_nodes)
                out[(size_t)node * D + lane] = acc[r];   // coalesced
        }
        buf ^= 1;
    }
}

// ---------------------------------------------------------------------------
extern "C" void kernel_launch(void* const* d_in, const int* in_sizes, int n_in,
                              void* d_out, int out_size) {
    const float* x = (const float*)d_in[0];
    const int* edge_index = (const int*)d_in[1];
    const float* W = (const float*)d_in[2];
    float* out = (float*)d_out;

    int n_edges = in_sizes[1] / 2;
    int n_nodes = in_sizes[0] / D;

    float* agg;
    cudaGetSymbolAddress((void**)&agg, g_agg);

    // 1) zero the aggregation buffer
    cudaMemsetAsync(agg, 0, (size_t)N_NODES * D * sizeof(float));

    // 2) scatter-add: 4 edges per warp, vector RED, persistent grid
    {
        int threads = 256;   // 8 warps
        int blocks  = 4736;
        scatter_kernel<<<blocks, threads>>>((const float4*)x, edge_index, agg,
                                            n_edges);
    }

    // 3) GEMM: persistent double-buffered blocks (~4/SM), 64-node tiles
    {
        gemm_kernel<<<592, 256>>>((const float4*)agg, W, out, n_nodes);
    }
}